// round 4
// baseline (speedup 1.0000x reference)
#include <cuda_runtime.h>
#include <cuda_bf16.h>
#include <cstdint>
#include <math.h>

#define NB 16
#define NC 64
#define IMG 256
#define PLANE 65536

// scratch (device globals — no allocation allowed)
__device__ float g_y[NB * 64 * NC];      // [b][n][c] pooled tokens
__device__ float g_dist[NB * 64 * 64];   // [b][n][m] softmax attention

// ---------------------------------------------------------------------------
// Kernel A: adaptive avg pool 8x8 — one CTA per (b,c) plane, coalesced reads.
// ---------------------------------------------------------------------------
__global__ __launch_bounds__(256) void pool_kernel(const float* __restrict__ x) {
    int bc = blockIdx.x;
    const float* plane = x + (size_t)bc * PLANE;
    int t = threadIdx.x;
    int warp = t >> 5, lane = t & 31;

    __shared__ float wsum[64];
    if (t < 64) wsum[t] = 0.f;
    __syncthreads();

    for (int pass = 0; pass < 32; pass++) {
        int row = pass * 8 + warp;
        const float4* rp = (const float4*)(plane + row * IMG);
        float4 v1 = rp[lane];
        float4 v2 = rp[lane + 32];
        float s1 = v1.x + v1.y + v1.z + v1.w;
        float s2 = v2.x + v2.y + v2.z + v2.w;
        s1 += __shfl_xor_sync(~0u, s1, 4);
        s1 += __shfl_xor_sync(~0u, s1, 2);
        s1 += __shfl_xor_sync(~0u, s1, 1);
        s2 += __shfl_xor_sync(~0u, s2, 4);
        s2 += __shfl_xor_sync(~0u, s2, 2);
        s2 += __shfl_xor_sync(~0u, s2, 1);
        if ((lane & 7) == 0) {
            int wr = row >> 5;
            atomicAdd(&wsum[wr * 8 + (lane >> 3)], s1);
            atomicAdd(&wsum[wr * 8 + (lane >> 3) + 4], s2);
        }
    }
    __syncthreads();
    if (t < 64) {
        int b = bc >> 6, c = bc & 63;
        g_y[((size_t)b * 64 + t) * NC + c] = wsum[t] * (1.0f / 1024.0f);
    }
}

// ---------------------------------------------------------------------------
// Kernel B: q = yWq^T, k = yWk^T, dist = softmax(q k^T / 8). One CTA per batch.
// ---------------------------------------------------------------------------
__global__ __launch_bounds__(256) void dist_kernel(const float* __restrict__ Wq,
                                                   const float* __restrict__ Wk) {
    __shared__ float sY[4096];
    __shared__ float sA[4096];
    __shared__ float sB2[4096];
    int b = blockIdx.x, t = threadIdx.x;

    for (int idx = t; idx < 4096; idx += 256) {
        sY[idx]  = g_y[b * 4096 + idx];
        sA[idx]  = Wq[idx];
        sB2[idx] = Wk[idx];
    }
    __syncthreads();

    int n = t >> 2;
    int kk = (t & 3) * 16;

    float qv[16], kv[16];
    #pragma unroll
    for (int e = 0; e < 16; e++) {
        float aq = 0.f, ak = 0.f;
        const float* yr = &sY[n * 64];
        const float* wq = &sA[(kk + e) * 64];
        const float* wk = &sB2[(kk + e) * 64];
        #pragma unroll
        for (int c = 0; c < 64; c++) {
            aq = fmaf(yr[c], wq[c], aq);
            ak = fmaf(yr[c], wk[c], ak);
        }
        qv[e] = aq; kv[e] = ak;
    }
    __syncthreads();
    #pragma unroll
    for (int e = 0; e < 16; e++) {
        sA[n * 64 + kk + e]  = qv[e];
        sB2[n * 64 + kk + e] = kv[e];
    }
    __syncthreads();

    float sv[16];
    #pragma unroll
    for (int e = 0; e < 16; e++) {
        int m = kk + e;
        float s = 0.f;
        const float* qr = &sA[n * 64];
        const float* kr = &sB2[m * 64];
        #pragma unroll
        for (int k = 0; k < 64; k++) s = fmaf(qr[k], kr[k], s);
        sv[e] = s * 0.125f;
    }
    __syncthreads();
    #pragma unroll
    for (int e = 0; e < 16; e++) sY[n * 64 + kk + e] = sv[e];
    __syncthreads();

    int warp = t >> 5, lane = t & 31;
    for (int j = 0; j < 8; j++) {
        int row = warp * 8 + j;
        float a  = sY[row * 64 + lane];
        float c2 = sY[row * 64 + lane + 32];
        float mx = fmaxf(a, c2);
        for (int d = 16; d >= 1; d >>= 1) mx = fmaxf(mx, __shfl_xor_sync(~0u, mx, d));
        float ea = expf(a - mx), eb = expf(c2 - mx);
        float s = ea + eb;
        for (int d = 16; d >= 1; d >>= 1) s += __shfl_xor_sync(~0u, s, d);
        float inv = 1.0f / s;
        g_dist[b * 4096 + row * 64 + lane]      = ea * inv;
        g_dist[b * 4096 + row * 64 + lane + 32] = eb * inv;
    }
}

// ---------------------------------------------------------------------------
// Kernel C (att): mma.sync bf16 hi/lo-split GEMM.
// CTA = (b, c, ig). OUT[64 n][256 px] = dist[64x64] @ V[64x256].
// A (dist) hi/lo in smem (144B rows); B (V) hi/lo k-major (528B rows).
// Per kk: load Ah,Al (8 LDSM.x4) + Bh,Bl (8 LDSM.x2), 48 HMMA.
// Epilogue: acc -> smem stage (reuses B region, bank-rotated) -> STG.128.
// ---------------------------------------------------------------------------
#define SM_BH 0
#define SM_BL 33792
#define SM_AH 67584
#define SM_AL 76800
#define SMEM_ATT 86016
#define STAGE_PITCH 1056   // 264 floats; 64 rows * 1056 = 67584 = fits B region

__device__ __forceinline__ uint32_t smem_u32(const void* p) {
    uint32_t a;
    asm("{ .reg .u64 t; cvta.to.shared.u64 t, %1; cvt.u32.u64 %0, t; }"
        : "=r"(a) : "l"(p));
    return a;
}
__device__ __forceinline__ uint32_t pack_bf16(float lo, float hi) {
    uint32_t r;
    asm("cvt.rn.bf16x2.f32 %0, %1, %2;" : "=r"(r) : "f"(hi), "f"(lo));
    return r;
}

__global__ void __launch_bounds__(256, 2) att_kernel(const float* __restrict__ x,
                                                     float* __restrict__ out) {
    extern __shared__ char sm[];
    uint32_t sbase = smem_u32(sm);
    int t = threadIdx.x;
    int wid = t >> 5, lane = t & 31;

    int blk = blockIdx.x;
    int ig = blk & 3;
    int c  = (blk >> 2) & 63;
    int b  = blk >> 8;

    const float* xplane = x + (size_t)(b * 64 + c) * PLANE;

    // ---- B build: 64 source image rows; warp w builds rows sr = w*8..w*8+7 ----
    #pragma unroll
    for (int it = 0; it < 8; it++) {
        int sr = wid * 8 + it;
        int mr = sr >> 3, il = sr & 7;
        const float4* xr = (const float4*)(xplane + (size_t)(mr * 32 + ig * 8 + il) * IMG);
        #pragma unroll
        for (int rep = 0; rep < 2; rep++) {
            int l2 = lane + rep * 32;
            float4 v = xr[l2];
            uint32_t h01 = pack_bf16(v.x, v.y);
            uint32_t h23 = pack_bf16(v.z, v.w);
            float lx = v.x - __uint_as_float(h01 << 16);
            float ly = v.y - __uint_as_float(h01 & 0xffff0000u);
            float lz = v.z - __uint_as_float(h23 << 16);
            float lw = v.w - __uint_as_float(h23 & 0xffff0000u);
            uint32_t l01 = pack_bf16(lx, ly);
            uint32_t l23 = pack_bf16(lz, lw);
            int mc = l2 >> 3, jc0 = (l2 & 7) * 4;
            uint32_t off = (uint32_t)(mr * 8 + mc) * 528u + (uint32_t)(il * 32 + jc0) * 2u;
            *(uint2*)(sm + SM_BH + off) = make_uint2(h01, h23);
            *(uint2*)(sm + SM_BL + off) = make_uint2(l01, l23);
        }
    }

    // ---- A build: dist hi/lo -> smem. Thread t: row t>>2, 16 cols at (t&3)*16 ----
    {
        int row = t >> 2, q = (t & 3) * 16;
        const float4* dr = (const float4*)(g_dist + b * 4096 + row * 64 + q);
        uint32_t hv[8], lv[8];
        #pragma unroll
        for (int i = 0; i < 4; i++) {
            float4 dv = dr[i];
            uint32_t h0 = pack_bf16(dv.x, dv.y);
            uint32_t h1 = pack_bf16(dv.z, dv.w);
            float lx = dv.x - __uint_as_float(h0 << 16);
            float ly = dv.y - __uint_as_float(h0 & 0xffff0000u);
            float lz = dv.z - __uint_as_float(h1 << 16);
            float lw = dv.w - __uint_as_float(h1 & 0xffff0000u);
            hv[2*i] = h0; hv[2*i+1] = h1;
            lv[2*i] = pack_bf16(lx, ly); lv[2*i+1] = pack_bf16(lz, lw);
        }
        uint32_t off = (uint32_t)row * 144u + (uint32_t)q * 2u;
        *(uint4*)(sm + SM_AH + off)      = make_uint4(hv[0], hv[1], hv[2], hv[3]);
        *(uint4*)(sm + SM_AH + off + 16) = make_uint4(hv[4], hv[5], hv[6], hv[7]);
        *(uint4*)(sm + SM_AL + off)      = make_uint4(lv[0], lv[1], lv[2], lv[3]);
        *(uint4*)(sm + SM_AL + off + 16) = make_uint4(lv[4], lv[5], lv[6], lv[7]);
    }
    __syncthreads();

    // ---- MMA mainloop (A fragments loaded once per kk) ----
    float acc[4][4][4];
    #pragma unroll
    for (int mt = 0; mt < 4; mt++)
        #pragma unroll
        for (int nt = 0; nt < 4; nt++) {
            acc[mt][nt][0] = 0.f; acc[mt][nt][1] = 0.f;
            acc[mt][nt][2] = 0.f; acc[mt][nt][3] = 0.f;
        }

    int row16 = lane & 15;
    uint32_t aH = sbase + SM_AH + (uint32_t)row16 * 144u + (uint32_t)((lane >> 4) * 8) * 2u;
    uint32_t aL = sbase + SM_AL + (uint32_t)row16 * 144u + (uint32_t)((lane >> 4) * 8) * 2u;
    uint32_t bH = sbase + SM_BH + (uint32_t)row16 * 528u + (uint32_t)(wid * 32) * 2u;
    uint32_t bL = sbase + SM_BL + (uint32_t)row16 * 528u + (uint32_t)(wid * 32) * 2u;

    #pragma unroll
    for (int kk = 0; kk < 4; kk++) {
        uint32_t ah[4][4], al[4][4];
        #pragma unroll
        for (int mt = 0; mt < 4; mt++) {
            uint32_t addr = aH + (uint32_t)(mt * 16) * 144u + (uint32_t)(kk * 32);
            asm volatile("ldmatrix.sync.aligned.m8n8.x4.shared.b16 {%0,%1,%2,%3}, [%4];"
                         : "=r"(ah[mt][0]), "=r"(ah[mt][1]), "=r"(ah[mt][2]), "=r"(ah[mt][3])
                         : "r"(addr));
        }
        #pragma unroll
        for (int mt = 0; mt < 4; mt++) {
            uint32_t addr = aL + (uint32_t)(mt * 16) * 144u + (uint32_t)(kk * 32);
            asm volatile("ldmatrix.sync.aligned.m8n8.x4.shared.b16 {%0,%1,%2,%3}, [%4];"
                         : "=r"(al[mt][0]), "=r"(al[mt][1]), "=r"(al[mt][2]), "=r"(al[mt][3])
                         : "r"(addr));
        }
        uint32_t bh[4][2];
        #pragma unroll
        for (int nt = 0; nt < 4; nt++) {
            uint32_t addr = bH + (uint32_t)(kk * 16) * 528u + (uint32_t)(nt * 16);
            asm volatile("ldmatrix.sync.aligned.m8n8.x2.trans.shared.b16 {%0,%1}, [%2];"
                         : "=r"(bh[nt][0]), "=r"(bh[nt][1]) : "r"(addr));
        }
        #pragma unroll
        for (int mt = 0; mt < 4; mt++)
            #pragma unroll
            for (int nt = 0; nt < 4; nt++)
                asm volatile(
                    "mma.sync.aligned.m16n8k16.row.col.f32.bf16.bf16.f32 "
                    "{%0,%1,%2,%3}, {%4,%5,%6,%7}, {%8,%9}, {%0,%1,%2,%3};"
                    : "+f"(acc[mt][nt][0]), "+f"(acc[mt][nt][1]),
                      "+f"(acc[mt][nt][2]), "+f"(acc[mt][nt][3])
                    : "r"(ah[mt][0]), "r"(ah[mt][1]), "r"(ah[mt][2]), "r"(ah[mt][3]),
                      "r"(bh[nt][0]), "r"(bh[nt][1]));
        uint32_t bl[4][2];
        #pragma unroll
        for (int nt = 0; nt < 4; nt++) {
            uint32_t addr = bL + (uint32_t)(kk * 16) * 528u + (uint32_t)(nt * 16);
            asm volatile("ldmatrix.sync.aligned.m8n8.x2.trans.shared.b16 {%0,%1}, [%2];"
                         : "=r"(bl[nt][0]), "=r"(bl[nt][1]) : "r"(addr));
        }
        #pragma unroll
        for (int mt = 0; mt < 4; mt++)
            #pragma unroll
            for (int nt = 0; nt < 4; nt++)
                asm volatile(
                    "mma.sync.aligned.m16n8k16.row.col.f32.bf16.bf16.f32 "
                    "{%0,%1,%2,%3}, {%4,%5,%6,%7}, {%8,%9}, {%0,%1,%2,%3};"
                    : "+f"(acc[mt][nt][0]), "+f"(acc[mt][nt][1]),
                      "+f"(acc[mt][nt][2]), "+f"(acc[mt][nt][3])
                    : "r"(al[mt][0]), "r"(al[mt][1]), "r"(al[mt][2]), "r"(al[mt][3]),
                      "r"(bh[nt][0]), "r"(bh[nt][1]));
        #pragma unroll
        for (int mt = 0; mt < 4; mt++)
            #pragma unroll
            for (int nt = 0; nt < 4; nt++)
                asm volatile(
                    "mma.sync.aligned.m16n8k16.row.col.f32.bf16.bf16.f32 "
                    "{%0,%1,%2,%3}, {%4,%5,%6,%7}, {%8,%9}, {%0,%1,%2,%3};"
                    : "+f"(acc[mt][nt][0]), "+f"(acc[mt][nt][1]),
                      "+f"(acc[mt][nt][2]), "+f"(acc[mt][nt][3])
                    : "r"(ah[mt][0]), "r"(ah[mt][1]), "r"(ah[mt][2]), "r"(ah[mt][3]),
                      "r"(bl[nt][0]), "r"(bl[nt][1]));
    }

    // ---- epilogue: acc -> smem stage (reuse B region) -> coalesced STG.128 ----
    __syncthreads();   // all warps done reading B
    {
        int g = lane >> 2, tig = lane & 3;
        #pragma unroll
        for (int mt = 0; mt < 4; mt++) {
            #pragma unroll
            for (int nt = 0; nt < 4; nt++) {
                int dd = nt * 8 + tig * 2;
                int inner = (dd + 8 * g) & 31;            // bank rotation per chunk
                uint32_t base = (uint32_t)g * 128u + (uint32_t)inner * 4u;
                uint32_t offA = (uint32_t)((2 * mt) * 8 + wid) * STAGE_PITCH + base;
                uint32_t offB = (uint32_t)((2 * mt + 1) * 8 + wid) * STAGE_PITCH + base;
                *(float2*)(sm + offA) = make_float2(acc[mt][nt][0], acc[mt][nt][1]);
                *(float2*)(sm + offB) = make_float2(acc[mt][nt][2], acc[mt][nt][3]);
            }
        }
    }
    __syncthreads();
    {
        float* oplane = out + (size_t)(b * 64 + c) * PLANE;
        #pragma unroll
        for (int q = 0; q < 8; q++) {
            int sr = wid * 8 + q;
            float* orow = oplane + (size_t)(wid * 32 + ig * 8 + q) * IMG;
            #pragma unroll
            for (int h = 0; h < 2; h++) {
                int l2 = lane + h * 32;
                int pc = l2 >> 3;
                int j  = (4 * l2) & 31;
                int inner = (j + 8 * pc) & 31;
                float4 v = *(const float4*)(sm + (uint32_t)sr * STAGE_PITCH
                                               + (uint32_t)pc * 128u + (uint32_t)inner * 4u);
                __stcs((float4*)(orow + 4 * l2), v);
            }
        }
    }
}

extern "C" void kernel_launch(void* const* d_in, const int* in_sizes, int n_in,
                              void* d_out, int out_size) {
    const float* x  = (const float*)d_in[0];
    const float* Wq = (const float*)d_in[1];
    const float* Wk = (const float*)d_in[2];
    float* out = (float*)d_out;

    cudaFuncSetAttribute(att_kernel, cudaFuncAttributeMaxDynamicSharedMemorySize, SMEM_ATT);

    pool_kernel<<<NB * NC, 256>>>(x);
    dist_kernel<<<NB, 256>>>(Wq, Wk);
    att_kernel<<<NB * NC * 4, 256, SMEM_ATT>>>(x, out);
}

// round 5
// speedup vs baseline: 1.2085x; 1.2085x over previous
#include <cuda_runtime.h>
#include <cuda_fp16.h>
#include <cstdint>
#include <math.h>

#define NB 16
#define NC 64
#define IMG 256
#define PLANE 65536

// scratch (device globals — no allocation allowed)
__device__ float g_y[NB * 64 * NC];      // [b][n][c] pooled tokens
__device__ float g_dist[NB * 64 * 64];   // [b][n][m] softmax attention

// ---------------------------------------------------------------------------
// Kernel A: adaptive avg pool 8x8 — one CTA per (b,c) plane, coalesced reads.
// ---------------------------------------------------------------------------
__global__ __launch_bounds__(256) void pool_kernel(const float* __restrict__ x) {
    int bc = blockIdx.x;
    const float* plane = x + (size_t)bc * PLANE;
    int t = threadIdx.x;
    int warp = t >> 5, lane = t & 31;

    __shared__ float wsum[64];
    if (t < 64) wsum[t] = 0.f;
    __syncthreads();

    for (int pass = 0; pass < 32; pass++) {
        int row = pass * 8 + warp;
        const float4* rp = (const float4*)(plane + row * IMG);
        float4 v1 = rp[lane];
        float4 v2 = rp[lane + 32];
        float s1 = v1.x + v1.y + v1.z + v1.w;
        float s2 = v2.x + v2.y + v2.z + v2.w;
        s1 += __shfl_xor_sync(~0u, s1, 4);
        s1 += __shfl_xor_sync(~0u, s1, 2);
        s1 += __shfl_xor_sync(~0u, s1, 1);
        s2 += __shfl_xor_sync(~0u, s2, 4);
        s2 += __shfl_xor_sync(~0u, s2, 2);
        s2 += __shfl_xor_sync(~0u, s2, 1);
        if ((lane & 7) == 0) {
            int wr = row >> 5;
            atomicAdd(&wsum[wr * 8 + (lane >> 3)], s1);
            atomicAdd(&wsum[wr * 8 + (lane >> 3) + 4], s2);
        }
    }
    __syncthreads();
    if (t < 64) {
        int b = bc >> 6, c = bc & 63;
        g_y[((size_t)b * 64 + t) * NC + c] = wsum[t] * (1.0f / 1024.0f);
    }
}

// ---------------------------------------------------------------------------
// Kernel B: q = yWq^T, k = yWk^T, dist = softmax(q k^T / 8). One CTA per batch.
// ---------------------------------------------------------------------------
__global__ __launch_bounds__(256) void dist_kernel(const float* __restrict__ Wq,
                                                   const float* __restrict__ Wk) {
    __shared__ float sY[4096];
    __shared__ float sA[4096];
    __shared__ float sB2[4096];
    int b = blockIdx.x, t = threadIdx.x;

    for (int idx = t; idx < 4096; idx += 256) {
        sY[idx]  = g_y[b * 4096 + idx];
        sA[idx]  = Wq[idx];
        sB2[idx] = Wk[idx];
    }
    __syncthreads();

    int n = t >> 2;
    int kk = (t & 3) * 16;

    float qv[16], kv[16];
    #pragma unroll
    for (int e = 0; e < 16; e++) {
        float aq = 0.f, ak = 0.f;
        const float* yr = &sY[n * 64];
        const float* wq = &sA[(kk + e) * 64];
        const float* wk = &sB2[(kk + e) * 64];
        #pragma unroll
        for (int c = 0; c < 64; c++) {
            aq = fmaf(yr[c], wq[c], aq);
            ak = fmaf(yr[c], wk[c], ak);
        }
        qv[e] = aq; kv[e] = ak;
    }
    __syncthreads();
    #pragma unroll
    for (int e = 0; e < 16; e++) {
        sA[n * 64 + kk + e]  = qv[e];
        sB2[n * 64 + kk + e] = kv[e];
    }
    __syncthreads();

    float sv[16];
    #pragma unroll
    for (int e = 0; e < 16; e++) {
        int m = kk + e;
        float s = 0.f;
        const float* qr = &sA[n * 64];
        const float* kr = &sB2[m * 64];
        #pragma unroll
        for (int k = 0; k < 64; k++) s = fmaf(qr[k], kr[k], s);
        sv[e] = s * 0.125f;
    }
    __syncthreads();
    #pragma unroll
    for (int e = 0; e < 16; e++) sY[n * 64 + kk + e] = sv[e];
    __syncthreads();

    int warp = t >> 5, lane = t & 31;
    for (int j = 0; j < 8; j++) {
        int row = warp * 8 + j;
        float a  = sY[row * 64 + lane];
        float c2 = sY[row * 64 + lane + 32];
        float mx = fmaxf(a, c2);
        for (int d = 16; d >= 1; d >>= 1) mx = fmaxf(mx, __shfl_xor_sync(~0u, mx, d));
        float ea = expf(a - mx), eb = expf(c2 - mx);
        float s = ea + eb;
        for (int d = 16; d >= 1; d >>= 1) s += __shfl_xor_sync(~0u, s, d);
        float inv = 1.0f / s;
        g_dist[b * 4096 + row * 64 + lane]      = ea * inv;
        g_dist[b * 4096 + row * 64 + lane + 32] = eb * inv;
    }
}

// ---------------------------------------------------------------------------
// Kernel C (att): mma.sync fp16 2-pass GEMM (A = dist split hi/lo fp16, exact
// to 2^-22; B = x as single fp16). OUT[64 n][256 px] = dist[64x64] @ V[64x256].
// Per kk: 4 B-LDSM.x2 (shared by both passes) + 2x(4 A-LDSM.x4 + 16 HMMA).
// Epilogue: direct scatter (32B sectors fully used).
// ---------------------------------------------------------------------------
#define SM_B  0
#define SM_AH 33792
#define SM_AL 43008
#define SMEM_ATT 52224

__device__ __forceinline__ uint32_t smem_u32(const void* p) {
    uint32_t a;
    asm("{ .reg .u64 t; cvta.to.shared.u64 t, %1; cvt.u32.u64 %0, t; }"
        : "=r"(a) : "l"(p));
    return a;
}
__device__ __forceinline__ uint32_t pack_f16(float lo, float hi) {
    __half2 h = __floats2half2_rn(lo, hi);
    return *(uint32_t*)&h;
}

__global__ void __launch_bounds__(256, 2) att_kernel(const float* __restrict__ x,
                                                     float* __restrict__ out) {
    extern __shared__ char sm[];
    uint32_t sbase = smem_u32(sm);
    int t = threadIdx.x;
    int wid = t >> 5, lane = t & 31;

    int blk = blockIdx.x;
    int ig = blk & 3;
    int c  = (blk >> 2) & 63;
    int b  = blk >> 8;

    const float* xplane = x + (size_t)(b * 64 + c) * PLANE;

    // ---- B build: front-batch all 16 LDG.128, then convert+store ----
    float4 vv[8][2];
    #pragma unroll
    for (int it = 0; it < 8; it++) {
        int sr = wid * 8 + it;
        int mr = sr >> 3, il = sr & 7;
        const float4* xr = (const float4*)(xplane + (size_t)(mr * 32 + ig * 8 + il) * IMG);
        vv[it][0] = xr[lane];
        vv[it][1] = xr[lane + 32];
    }
    #pragma unroll
    for (int it = 0; it < 8; it++) {
        int sr = wid * 8 + it;
        int mr = sr >> 3, il = sr & 7;
        #pragma unroll
        for (int rep = 0; rep < 2; rep++) {
            int l2 = lane + rep * 32;
            float4 v = vv[it][rep];
            uint32_t p01 = pack_f16(v.x, v.y);
            uint32_t p23 = pack_f16(v.z, v.w);
            int mc = l2 >> 3, jc0 = (l2 & 7) * 4;
            uint32_t off = (uint32_t)(mr * 8 + mc) * 528u + (uint32_t)(il * 32 + jc0) * 2u;
            *(uint2*)(sm + SM_B + off) = make_uint2(p01, p23);
        }
    }

    // ---- A build: dist fp16 hi/lo -> smem. Thread t: row t>>2, 16 cols ----
    {
        int row = t >> 2, q = (t & 3) * 16;
        const float4* dr = (const float4*)(g_dist + b * 4096 + row * 64 + q);
        uint32_t hv[8], lv[8];
        #pragma unroll
        for (int i = 0; i < 4; i++) {
            float4 dv = dr[i];
            __half2 h0 = __floats2half2_rn(dv.x, dv.y);
            __half2 h1 = __floats2half2_rn(dv.z, dv.w);
            float2 b0 = __half22float2(h0);
            float2 b1 = __half22float2(h1);
            __half2 l0 = __floats2half2_rn(dv.x - b0.x, dv.y - b0.y);
            __half2 l1 = __floats2half2_rn(dv.z - b1.x, dv.w - b1.y);
            hv[2*i]   = *(uint32_t*)&h0;
            hv[2*i+1] = *(uint32_t*)&h1;
            lv[2*i]   = *(uint32_t*)&l0;
            lv[2*i+1] = *(uint32_t*)&l1;
        }
        uint32_t off = (uint32_t)row * 144u + (uint32_t)q * 2u;
        *(uint4*)(sm + SM_AH + off)      = make_uint4(hv[0], hv[1], hv[2], hv[3]);
        *(uint4*)(sm + SM_AH + off + 16) = make_uint4(hv[4], hv[5], hv[6], hv[7]);
        *(uint4*)(sm + SM_AL + off)      = make_uint4(lv[0], lv[1], lv[2], lv[3]);
        *(uint4*)(sm + SM_AL + off + 16) = make_uint4(lv[4], lv[5], lv[6], lv[7]);
    }
    __syncthreads();

    // ---- MMA mainloop: B loaded once per kk, A hi then A lo ----
    float acc[4][4][4];
    #pragma unroll
    for (int mt = 0; mt < 4; mt++)
        #pragma unroll
        for (int nt = 0; nt < 4; nt++) {
            acc[mt][nt][0] = 0.f; acc[mt][nt][1] = 0.f;
            acc[mt][nt][2] = 0.f; acc[mt][nt][3] = 0.f;
        }

    int row16 = lane & 15;
    uint32_t aH = sbase + SM_AH + (uint32_t)row16 * 144u + (uint32_t)((lane >> 4) * 8) * 2u;
    uint32_t aL = sbase + SM_AL + (uint32_t)row16 * 144u + (uint32_t)((lane >> 4) * 8) * 2u;
    uint32_t bB = sbase + SM_B  + (uint32_t)row16 * 528u + (uint32_t)(wid * 32) * 2u;

    #pragma unroll
    for (int kk = 0; kk < 4; kk++) {
        uint32_t bh[4][2];
        #pragma unroll
        for (int nt = 0; nt < 4; nt++) {
            uint32_t addr = bB + (uint32_t)(kk * 16) * 528u + (uint32_t)(nt * 16);
            asm volatile("ldmatrix.sync.aligned.m8n8.x2.trans.shared.b16 {%0,%1}, [%2];"
                         : "=r"(bh[nt][0]), "=r"(bh[nt][1]) : "r"(addr));
        }
        #pragma unroll
        for (int mt = 0; mt < 4; mt++) {
            uint32_t af[4];
            uint32_t addr = aH + (uint32_t)(mt * 16) * 144u + (uint32_t)(kk * 32);
            asm volatile("ldmatrix.sync.aligned.m8n8.x4.shared.b16 {%0,%1,%2,%3}, [%4];"
                         : "=r"(af[0]), "=r"(af[1]), "=r"(af[2]), "=r"(af[3]) : "r"(addr));
            #pragma unroll
            for (int nt = 0; nt < 4; nt++)
                asm volatile(
                    "mma.sync.aligned.m16n8k16.row.col.f32.f16.f16.f32 "
                    "{%0,%1,%2,%3}, {%4,%5,%6,%7}, {%8,%9}, {%0,%1,%2,%3};"
                    : "+f"(acc[mt][nt][0]), "+f"(acc[mt][nt][1]),
                      "+f"(acc[mt][nt][2]), "+f"(acc[mt][nt][3])
                    : "r"(af[0]), "r"(af[1]), "r"(af[2]), "r"(af[3]),
                      "r"(bh[nt][0]), "r"(bh[nt][1]));
        }
        #pragma unroll
        for (int mt = 0; mt < 4; mt++) {
            uint32_t af[4];
            uint32_t addr = aL + (uint32_t)(mt * 16) * 144u + (uint32_t)(kk * 32);
            asm volatile("ldmatrix.sync.aligned.m8n8.x4.shared.b16 {%0,%1,%2,%3}, [%4];"
                         : "=r"(af[0]), "=r"(af[1]), "=r"(af[2]), "=r"(af[3]) : "r"(addr));
            #pragma unroll
            for (int nt = 0; nt < 4; nt++)
                asm volatile(
                    "mma.sync.aligned.m16n8k16.row.col.f32.f16.f16.f32 "
                    "{%0,%1,%2,%3}, {%4,%5,%6,%7}, {%8,%9}, {%0,%1,%2,%3};"
                    : "+f"(acc[mt][nt][0]), "+f"(acc[mt][nt][1]),
                      "+f"(acc[mt][nt][2]), "+f"(acc[mt][nt][3])
                    : "r"(af[0]), "r"(af[1]), "r"(af[2]), "r"(af[3]),
                      "r"(bh[nt][0]), "r"(bh[nt][1]));
        }
    }

    // ---- epilogue: direct scatter (8 x 32B fully-used sectors per STG) ----
    {
        int g = lane >> 2, tig = lane & 3;
        float* oplane = out + (size_t)(b * 64 + c) * PLANE;
        int rowbase = ig * 8 + wid;  // il = wid
        #pragma unroll
        for (int mt = 0; mt < 4; mt++) {
            #pragma unroll
            for (int nt = 0; nt < 4; nt++) {
                int jc = nt * 8 + tig * 2;
                int n1 = mt * 16 + g;
                int n2 = n1 + 8;
                float* p1 = oplane + (size_t)((n1 >> 3) * 32 + rowbase) * IMG
                          + (n1 & 7) * 32 + jc;
                float* p2 = oplane + (size_t)((n2 >> 3) * 32 + rowbase) * IMG
                          + (n2 & 7) * 32 + jc;
                *(float2*)p1 = make_float2(acc[mt][nt][0], acc[mt][nt][1]);
                *(float2*)p2 = make_float2(acc[mt][nt][2], acc[mt][nt][3]);
            }
        }
    }
}

extern "C" void kernel_launch(void* const* d_in, const int* in_sizes, int n_in,
                              void* d_out, int out_size) {
    const float* x  = (const float*)d_in[0];
    const float* Wq = (const float*)d_in[1];
    const float* Wk = (const float*)d_in[2];
    float* out = (float*)d_out;

    cudaFuncSetAttribute(att_kernel, cudaFuncAttributeMaxDynamicSharedMemorySize, SMEM_ATT);

    pool_kernel<<<NB * NC, 256>>>(x);
    dist_kernel<<<NB, 256>>>(Wq, Wk);
    att_kernel<<<NB * NC * 4, 256, SMEM_ATT>>>(x, out);
}

// round 7
// speedup vs baseline: 1.2330x; 1.0203x over previous
#include <cuda_runtime.h>
#include <cuda_fp16.h>
#include <cstdint>
#include <math.h>

#define NB 16
#define NC 64
#define IMG 256
#define PLANE 65536

// scratch (device globals — no allocation allowed)
__device__ float g_y[NB * 64 * NC];                 // [b][n][c] pooled tokens
__device__ unsigned long long g_xpack[16777216];    // x as fp16, [bc][ig][k=64][px=256] (134MB)
__device__ __align__(16) unsigned char g_Apack[NB * 18432]; // dist fp16 hi(9216)+lo(9216), 144B rows

__device__ __forceinline__ uint32_t smem_u32(const void* p) {
    uint32_t a;
    asm("{ .reg .u64 t; cvta.to.shared.u64 t, %1; cvt.u32.u64 %0, t; }"
        : "=r"(a) : "l"(p));
    return a;
}

// ---------------------------------------------------------------------------
// Kernel A: adaptive avg pool 8x8 + fp16 windowed repack of x.
// One CTA per (b,c) plane. row = mr*32 + ig*8 + il; warp = il, pass = mr*4+ig.
// Repack layout (u64 units): g_xpack[bc*16384 + ig*4096 + k*64 + px/4],
// k = mr*8+mc, px = il*32+jc.
// ---------------------------------------------------------------------------
__global__ __launch_bounds__(256) void pool_kernel(const float* __restrict__ x) {
    int bc = blockIdx.x;
    const float* plane = x + (size_t)bc * PLANE;
    int t = threadIdx.x;
    int warp = t >> 5, lane = t & 31;

    __shared__ float wsum[64];
    if (t < 64) wsum[t] = 0.f;
    __syncthreads();

    int mc1 = lane >> 3;               // window col for first float4 (0..3)
    int jq  = lane & 7;                // jc/4 within window
    unsigned long long* xp = g_xpack + (size_t)bc * 16384;

    for (int pass = 0; pass < 32; pass++) {
        int row = pass * 8 + warp;
        int mr = pass >> 2, ig = pass & 3;
        const float4* rp = (const float4*)(plane + row * IMG);
        float4 v1 = rp[lane];
        float4 v2 = rp[lane + 32];

        // fp16 repack (half4 = one u64 per float4)
        {
            __half2 a0 = __floats2half2_rn(v1.x, v1.y);
            __half2 a1 = __floats2half2_rn(v1.z, v1.w);
            __half2 b0 = __floats2half2_rn(v2.x, v2.y);
            __half2 b1 = __floats2half2_rn(v2.z, v2.w);
            unsigned long long u1 = ((unsigned long long)*(uint32_t*)&a1 << 32) | *(uint32_t*)&a0;
            unsigned long long u2 = ((unsigned long long)*(uint32_t*)&b1 << 32) | *(uint32_t*)&b0;
            xp[ig * 4096 + (mr * 8 + mc1) * 64 + warp * 8 + jq]     = u1;
            xp[ig * 4096 + (mr * 8 + mc1 + 4) * 64 + warp * 8 + jq] = u2;
        }

        float s1 = v1.x + v1.y + v1.z + v1.w;
        float s2 = v2.x + v2.y + v2.z + v2.w;
        s1 += __shfl_xor_sync(~0u, s1, 4);
        s1 += __shfl_xor_sync(~0u, s1, 2);
        s1 += __shfl_xor_sync(~0u, s1, 1);
        s2 += __shfl_xor_sync(~0u, s2, 4);
        s2 += __shfl_xor_sync(~0u, s2, 2);
        s2 += __shfl_xor_sync(~0u, s2, 1);
        if ((lane & 7) == 0) {
            int wr = row >> 5;
            atomicAdd(&wsum[wr * 8 + (lane >> 3)], s1);
            atomicAdd(&wsum[wr * 8 + (lane >> 3) + 4], s2);
        }
    }
    __syncthreads();
    if (t < 64) {
        int b = bc >> 6, c = bc & 63;
        g_y[((size_t)b * 64 + t) * NC + c] = wsum[t] * (1.0f / 1024.0f);
    }
}

// ---------------------------------------------------------------------------
// Kernel B: q = yWq^T, k = yWk^T, dist = softmax(q k^T / 8). One CTA per batch.
// Output: A packed fp16 hi/lo, 144B rows (the att smem image), to g_Apack.
// ---------------------------------------------------------------------------
__global__ __launch_bounds__(256) void dist_kernel(const float* __restrict__ Wq,
                                                   const float* __restrict__ Wk) {
    __shared__ float sY[4096];
    __shared__ float sA[4096];
    __shared__ float sB2[4096];
    int b = blockIdx.x, t = threadIdx.x;

    for (int idx = t; idx < 4096; idx += 256) {
        sY[idx]  = g_y[b * 4096 + idx];
        sA[idx]  = Wq[idx];
        sB2[idx] = Wk[idx];
    }
    __syncthreads();

    int n = t >> 2;
    int kk = (t & 3) * 16;

    float qv[16], kv[16];
    #pragma unroll
    for (int e = 0; e < 16; e++) {
        float aq = 0.f, ak = 0.f;
        const float* yr = &sY[n * 64];
        const float* wq = &sA[(kk + e) * 64];
        const float* wk = &sB2[(kk + e) * 64];
        #pragma unroll
        for (int c = 0; c < 64; c++) {
            aq = fmaf(yr[c], wq[c], aq);
            ak = fmaf(yr[c], wk[c], ak);
        }
        qv[e] = aq; kv[e] = ak;
    }
    __syncthreads();
    #pragma unroll
    for (int e = 0; e < 16; e++) {
        sA[n * 64 + kk + e]  = qv[e];
        sB2[n * 64 + kk + e] = kv[e];
    }
    __syncthreads();

    float sv[16];
    #pragma unroll
    for (int e = 0; e < 16; e++) {
        int m = kk + e;
        float s = 0.f;
        const float* qr = &sA[n * 64];
        const float* kr = &sB2[m * 64];
        #pragma unroll
        for (int k = 0; k < 64; k++) s = fmaf(qr[k], kr[k], s);
        sv[e] = s * 0.125f;
    }
    __syncthreads();
    #pragma unroll
    for (int e = 0; e < 16; e++) sY[n * 64 + kk + e] = sv[e];
    __syncthreads();

    // softmax + fp16 hi/lo pack: lane covers col pair (2*lane, 2*lane+1)
    int warp = t >> 5, lane = t & 31;
    unsigned char* ap = g_Apack + b * 18432;
    for (int j = 0; j < 8; j++) {
        int row = warp * 8 + j;
        float2 v = *(const float2*)&sY[row * 64 + 2 * lane];
        float mx = fmaxf(v.x, v.y);
        for (int d = 16; d >= 1; d >>= 1) mx = fmaxf(mx, __shfl_xor_sync(~0u, mx, d));
        float e0 = expf(v.x - mx), e1 = expf(v.y - mx);
        float s = e0 + e1;
        for (int d = 16; d >= 1; d >>= 1) s += __shfl_xor_sync(~0u, s, d);
        float inv = 1.0f / s;
        e0 *= inv; e1 *= inv;
        __half2 h = __floats2half2_rn(e0, e1);
        float2 hf = __half22float2(h);
        __half2 l = __floats2half2_rn(e0 - hf.x, e1 - hf.y);
        *(uint32_t*)(ap + row * 144 + lane * 4)        = *(uint32_t*)&h;
        *(uint32_t*)(ap + 9216 + row * 144 + lane * 4) = *(uint32_t*)&l;
    }
}

// ---------------------------------------------------------------------------
// Kernel C (att): pure streaming fp16 GEMM. CTA = (b, c, ig, nh), 8192 CTAs.
// smem filled by cp.async only (A image from g_Apack, B tile from g_xpack),
// then ldmatrix + 64 HMMA/warp (A hi + A lo passes), scatter epilogue.
// Warp grid 2(wm) x 4(wn) over M64 x N128; warp tile 32x32; 32 acc regs.
// ---------------------------------------------------------------------------
#define SM_A 0            // 18432 B (hi 9216 + lo 9216), 144B rows
#define SM_B 18432        // 64 rows * 272B = 17408
#define SMEM_ATT 35840

__global__ void __launch_bounds__(256, 3) att_kernel(float* __restrict__ out) {
    extern __shared__ char sm[];
    uint32_t sbase = smem_u32(sm);
    int t = threadIdx.x;
    int wid = t >> 5, lane = t & 31;
    int wm = wid >> 2, wn = wid & 3;

    int blk = blockIdx.x;
    int nh = blk & 1;
    int ig = (blk >> 1) & 3;
    int c  = (blk >> 3) & 63;
    int b  = blk >> 9;

    // ---- async fills ----
    {
        const char* gA = (const char*)g_Apack + b * 18432;
        #pragma unroll
        for (int idx = t; idx < 1152; idx += 256) {
            uint32_t d = sbase + SM_A + idx * 16;
            asm volatile("cp.async.cg.shared.global [%0], [%1], 16;"
                         :: "r"(d), "l"(gA + idx * 16));
        }
        // (bc,ig) tile = 64 k-rows * 512B; take the nh half of each row (256B)
        const char* gB = (const char*)g_xpack
                       + ((size_t)((b * 64 + c) * 4 + ig)) * 32768 + nh * 256;
        #pragma unroll
        for (int idx = t; idx < 1024; idx += 256) {
            int row = idx >> 4, ch = idx & 15;
            uint32_t d = sbase + SM_B + row * 272 + ch * 16;
            asm volatile("cp.async.cg.shared.global [%0], [%1], 16;"
                         :: "r"(d), "l"(gB + row * 512 + ch * 16));
        }
        asm volatile("cp.async.commit_group;");
        asm volatile("cp.async.wait_group 0;" ::: "memory");
    }
    __syncthreads();

    // ---- MMA mainloop ----
    float acc[2][4][4];
    #pragma unroll
    for (int mt = 0; mt < 2; mt++)
        #pragma unroll
        for (int nt = 0; nt < 4; nt++) {
            acc[mt][nt][0] = 0.f; acc[mt][nt][1] = 0.f;
            acc[mt][nt][2] = 0.f; acc[mt][nt][3] = 0.f;
        }

    int row16 = lane & 15;
    uint32_t aH = sbase + SM_A + (uint32_t)(wm * 32 + row16) * 144u + (uint32_t)(lane >> 4) * 16u;
    uint32_t aL = aH + 9216u;
    uint32_t bB = sbase + SM_B + (uint32_t)row16 * 272u + (uint32_t)(wn * 64);

    #pragma unroll
    for (int kk = 0; kk < 4; kk++) {
        uint32_t bh[4][2];
        #pragma unroll
        for (int nt = 0; nt < 4; nt++) {
            uint32_t addr = bB + (uint32_t)(kk * 16) * 272u + (uint32_t)(nt * 16);
            asm volatile("ldmatrix.sync.aligned.m8n8.x2.trans.shared.b16 {%0,%1}, [%2];"
                         : "=r"(bh[nt][0]), "=r"(bh[nt][1]) : "r"(addr));
        }
        #pragma unroll
        for (int mt = 0; mt < 2; mt++) {
            uint32_t af[4];
            uint32_t addr = aH + (uint32_t)(mt * 16) * 144u + (uint32_t)(kk * 32);
            asm volatile("ldmatrix.sync.aligned.m8n8.x4.shared.b16 {%0,%1,%2,%3}, [%4];"
                         : "=r"(af[0]), "=r"(af[1]), "=r"(af[2]), "=r"(af[3]) : "r"(addr));
            #pragma unroll
            for (int nt = 0; nt < 4; nt++)
                asm volatile(
                    "mma.sync.aligned.m16n8k16.row.col.f32.f16.f16.f32 "
                    "{%0,%1,%2,%3}, {%4,%5,%6,%7}, {%8,%9}, {%0,%1,%2,%3};"
                    : "+f"(acc[mt][nt][0]), "+f"(acc[mt][nt][1]),
                      "+f"(acc[mt][nt][2]), "+f"(acc[mt][nt][3])
                    : "r"(af[0]), "r"(af[1]), "r"(af[2]), "r"(af[3]),
                      "r"(bh[nt][0]), "r"(bh[nt][1]));
        }
        #pragma unroll
        for (int mt = 0; mt < 2; mt++) {
            uint32_t af[4];
            uint32_t addr = aL + (uint32_t)(mt * 16) * 144u + (uint32_t)(kk * 32);
            asm volatile("ldmatrix.sync.aligned.m8n8.x4.shared.b16 {%0,%1,%2,%3}, [%4];"
                         : "=r"(af[0]), "=r"(af[1]), "=r"(af[2]), "=r"(af[3]) : "r"(addr));
            #pragma unroll
            for (int nt = 0; nt < 4; nt++)
                asm volatile(
                    "mma.sync.aligned.m16n8k16.row.col.f32.f16.f16.f32 "
                    "{%0,%1,%2,%3}, {%4,%5,%6,%7}, {%8,%9}, {%0,%1,%2,%3};"
                    : "+f"(acc[mt][nt][0]), "+f"(acc[mt][nt][1]),
                      "+f"(acc[mt][nt][2]), "+f"(acc[mt][nt][3])
                    : "r"(af[0]), "r"(af[1]), "r"(af[2]), "r"(af[3]),
                      "r"(bh[nt][0]), "r"(bh[nt][1]));
        }
    }

    // ---- epilogue: direct scatter (fully-used 32B sectors) ----
    {
        int g = lane >> 2, tig = lane & 3;
        float* oplane = out + (size_t)(b * 64 + c) * PLANE;
        int rowbase = ig * 8 + nh * 4 + wn;     // il = nh*4 + wn
        #pragma unroll
        for (int mt = 0; mt < 2; mt++) {
            #pragma unroll
            for (int nt = 0; nt < 4; nt++) {
                int jc = nt * 8 + tig * 2;
                int n1 = wm * 32 + mt * 16 + g;
                int n2 = n1 + 8;
                float* p1 = oplane + (size_t)((n1 >> 3) * 32 + rowbase) * IMG
                          + (n1 & 7) * 32 + jc;
                float* p2 = oplane + (size_t)((n2 >> 3) * 32 + rowbase) * IMG
                          + (n2 & 7) * 32 + jc;
                *(float2*)p1 = make_float2(acc[mt][nt][0], acc[mt][nt][1]);
                *(float2*)p2 = make_float2(acc[mt][nt][2], acc[mt][nt][3]);
            }
        }
    }
}

extern "C" void kernel_launch(void* const* d_in, const int* in_sizes, int n_in,
                              void* d_out, int out_size) {
    const float* x  = (const float*)d_in[0];
    const float* Wq = (const float*)d_in[1];
    const float* Wk = (const float*)d_in[2];
    float* out = (float*)d_out;

    cudaFuncSetAttribute(att_kernel, cudaFuncAttributeMaxDynamicSharedMemorySize, SMEM_ATT);

    pool_kernel<<<NB * NC, 256>>>(x);
    dist_kernel<<<NB, 256>>>(Wq, Wk);
    att_kernel<<<NB * NC * 8, 256, SMEM_ATT>>>(out);
}